// round 15
// baseline (speedup 1.0000x reference)
#include <cuda_runtime.h>
#include <cuda_bf16.h>
#include <cstdint>

// Problem constants
#define C_IN   8
#define C_OUT  16
#define N_IN   8192      // C_IN*32*32
#define N_OUT  16384     // C_OUT*32*32
#define ROWS   8193      // N_IN + 1
#define COLS   16385     // N_OUT + 1

#define LOHI_BLOCKS 64
#define NTHREADS    256
// Grid: [0,64) lo/hi, block 64 = bias row, [65, 65+4*8192) = quarter-rows of M.
#define GRID_TOTAL  (LOHI_BLOCKS + 1 + 4 * 8192)

__global__ __launch_bounds__(NTHREADS, 8)   // pin <=32 regs -> 8 blocks/SM
void conv_abs_kernel(const float* __restrict__ cl,     // concrete_lower, 8192
                     const float* __restrict__ cu,     // concrete_upper, 8192
                     const float* __restrict__ wgt,    // weights, 16*8*3*3 = 1152
                     const float* __restrict__ bias,   // 16
                     float* __restrict__ out)          // lo[16384] | hi[16384] | M[8193*16385]
{
    const int t = threadIdx.x;
    float* __restrict__ M = out + 2 * N_OUT;

    if (blockIdx.x < LOHI_BLOCKS) {
        // ---- lo/hi path (start of grid: latency hidden in the store ramp) ----
        __shared__ float s_w[72];
        int gid = blockIdx.x * NTHREADS + t;
        int c   = gid >> 10;
        int rem = gid & 1023;
        int i   = rem >> 5;
        int j   = rem & 31;
        if (t < 72) s_w[t] = wgt[c * 72 + t];   // block spans exactly one channel c
        __syncthreads();

        float accL = bias[c];
        float accH = accL;
        #pragma unroll
        for (int ci = 0; ci < C_IN; ci++) {
            #pragma unroll
            for (int kh = 0; kh < 3; kh++) {
                int y = i - 1 + kh;
                if ((unsigned)y >= 32u) continue;
                #pragma unroll
                for (int kw = 0; kw < 3; kw++) {
                    int x = j - 1 + kw;
                    if ((unsigned)x >= 32u) continue;
                    float w   = s_w[(ci * 3 + kh) * 3 + kw];
                    int   tap = ci * 1024 + y * 32 + x;
                    float l = __ldg(cl + tap);
                    float u = __ldg(cu + tap);
                    accL += w * (w > 0.f ? l : u);
                    accH += w * (w > 0.f ? u : l);
                }
            }
        }
        out[gid]         = accL;   // lo
        out[N_OUT + gid] = accH;   // hi
        return;
    }

    if (blockIdx.x == LOHI_BLOCKS) {
        // ---- bias row r == 8192 (base 16B-aligned: 8192*16385 % 4 == 0) ----
        float* __restrict__ brow = M + (size_t)8192 * (size_t)COLS;
        #pragma unroll 4
        for (unsigned q = t; q < 4096u; q += NTHREADS) {
            const unsigned col = 4u * q;
            const float b = __ldg(bias + (col >> 10));
            *reinterpret_cast<float4*>(brow + col) = make_float4(b, b, b, b);
        }
        if (t == 0) brow[16384] = 1.0f;
        return;
    }

    // ---- M fill: one block per QUARTER-row, two-phase (zero-stream, then patch) ----
    const unsigned qb = blockIdx.x - (LOHI_BLOCKS + 1);  // 0..32767
    const unsigned r  = qb >> 2;                          // row 0..8191
    const unsigned qt = qb & 3u;                          // quarter 0..3

    float* __restrict__ row = M + (size_t)r * (size_t)COLS;
    const unsigned cbeg  = qt * 4096u;
    const unsigned nelem = 4096u + (qt == 3u ? 1u : 0u);  // last quarter includes last col

    // Each quarter starts at flat offset ≡ r (mod 4): 16385%4==1, 4096%4==0.
    const unsigned p = (4u - (r & 3u)) & 3u;              // peel to 16B alignment
    if (t < (int)p) row[cbeg + t] = 0.f;

    const unsigned quads = (nelem - p) >> 2;              // ~1024
    float* __restrict__ ali = row + cbeg + p;
    const float4 z4 = make_float4(0.f, 0.f, 0.f, 0.f);
    #pragma unroll 4
    for (unsigned q = t; q < quads; q += NTHREADS)
        *reinterpret_cast<float4*>(ali + 4u * q) = z4;

    const unsigned tail_start = p + 4u * quads;
    const unsigned ntail = nelem - tail_start;            // 0..3 (incl. last col in qt 3)
    if (t < (int)ntail) row[cbeg + tail_start + t] = 0.f;

    __syncthreads();  // order phase-1 stores before phase-2 overwrites

    // Phase 2: patch this quarter's 36 taps (channels [4*qt, 4*qt+4)). r = (ci,y,x).
    if (t < 36) {
        const unsigned ci  = r >> 10;
        const unsigned y   = (r >> 5) & 31u;
        const unsigned x   = r & 31u;
        const unsigned c   = 4u * qt + (unsigned)t / 9u;
        const unsigned rem = (unsigned)t % 9u;
        const unsigned dy  = rem / 3u;
        const unsigned dx  = rem - dy * 3u;
        const int i = (int)y - 1 + (int)dy;
        const int j = (int)x - 1 + (int)dx;
        if ((unsigned)i < 32u && (unsigned)j < 32u) {
            const unsigned kh  = 2u - dy;
            const unsigned kw  = 2u - dx;
            const unsigned col = c * 1024u + (unsigned)i * 32u + (unsigned)j;  // in this quarter
            row[col] = __ldg(wgt + ((c * 8u + ci) * 3u + kh) * 3u + kw);
        }
    }
}

extern "C" void kernel_launch(void* const* d_in, const int* in_sizes, int n_in,
                              void* d_out, int out_size) {
    const float* cl   = (const float*)d_in[0];
    const float* cu   = (const float*)d_in[1];
    const float* wgt  = (const float*)d_in[2];
    const float* bias = (const float*)d_in[3];
    float* out = (float*)d_out;

    conv_abs_kernel<<<GRID_TOTAL, NTHREADS>>>(cl, cu, wgt, bias, out);
}

// round 16
// speedup vs baseline: 1.3543x; 1.3543x over previous
#include <cuda_runtime.h>
#include <cuda_bf16.h>
#include <cstdint>

// Problem constants
#define C_IN   8
#define C_OUT  16
#define N_IN   8192      // C_IN*32*32
#define N_OUT  16384     // C_OUT*32*32
#define ROWS   8193      // N_IN + 1
#define COLS   16385     // N_OUT + 1

#define LOHI_BLOCKS 64
#define NTHREADS    256
#define M_BLOCKS    8192   // each handles 2 half-row segments (k and k+8192)
#define GRID_TOTAL  (LOHI_BLOCKS + 1 + M_BLOCKS)

__global__ __launch_bounds__(NTHREADS, 8)   // pin <=32 regs -> 8 blocks/SM
void conv_abs_kernel(const float* __restrict__ cl,     // concrete_lower, 8192
                     const float* __restrict__ cu,     // concrete_upper, 8192
                     const float* __restrict__ wgt,    // weights, 16*8*3*3 = 1152
                     const float* __restrict__ bias,   // 16
                     float* __restrict__ out)          // lo[16384] | hi[16384] | M[8193*16385]
{
    const int t = threadIdx.x;
    float* __restrict__ M = out + 2 * N_OUT;

    if (blockIdx.x < LOHI_BLOCKS) {
        // ---- lo/hi path (start of grid: latency hidden in the store ramp) ----
        __shared__ float s_w[72];
        int gid = blockIdx.x * NTHREADS + t;
        int c   = gid >> 10;
        int rem = gid & 1023;
        int i   = rem >> 5;
        int j   = rem & 31;
        if (t < 72) s_w[t] = wgt[c * 72 + t];   // block spans exactly one channel c
        __syncthreads();

        float accL = bias[c];
        float accH = accL;
        #pragma unroll
        for (int ci = 0; ci < C_IN; ci++) {
            #pragma unroll
            for (int kh = 0; kh < 3; kh++) {
                int y = i - 1 + kh;
                if ((unsigned)y >= 32u) continue;
                #pragma unroll
                for (int kw = 0; kw < 3; kw++) {
                    int x = j - 1 + kw;
                    if ((unsigned)x >= 32u) continue;
                    float w   = s_w[(ci * 3 + kh) * 3 + kw];
                    int   tap = ci * 1024 + y * 32 + x;
                    float l = __ldg(cl + tap);
                    float u = __ldg(cu + tap);
                    accL += w * (w > 0.f ? l : u);
                    accH += w * (w > 0.f ? u : l);
                }
            }
        }
        out[gid]         = accL;   // lo
        out[N_OUT + gid] = accH;   // hi
        return;
    }

    if (blockIdx.x == LOHI_BLOCKS) {
        // ---- bias row r == 8192 (base 16B-aligned: 8192*16385 % 4 == 0) ----
        float* __restrict__ brow = M + (size_t)8192 * (size_t)COLS;
        #pragma unroll 4
        for (unsigned q = t; q < 4096u; q += NTHREADS) {
            const unsigned col = 4u * q;
            const float b = __ldg(bias + (col >> 10));
            *reinterpret_cast<float4*>(brow + col) = make_float4(b, b, b, b);
        }
        if (t == 0) brow[16384] = 1.0f;
        return;
    }

    // ---- M fill: each block zeros TWO far-apart half-row segments, one barrier,
    //      then patches both. Segment s: row = s>>1, half = s&1 (32KB each). ----
    const unsigned k = blockIdx.x - (LOHI_BLOCKS + 1);   // 0..8191

    #pragma unroll
    for (int seg = 0; seg < 2; seg++) {
        const unsigned s    = k + (unsigned)seg * 8192u; // 0..16383
        const unsigned r    = s >> 1;
        const unsigned half = s & 1u;
        float* __restrict__ base = M + (size_t)r * (size_t)COLS + half * 8192u;
        const unsigned nelem = half ? 8193u : 8192u;     // half 1 includes last col

        // Segment start flat offset ≡ r (mod 4): 16385%4==1, 8192%4==0.
        const unsigned p = (4u - (r & 3u)) & 3u;         // peel to 16B alignment
        if (t < (int)p) base[t] = 0.f;

        const unsigned quads = (nelem - p) >> 2;         // ~2048
        float* __restrict__ ali = base + p;
        const float4 z4 = make_float4(0.f, 0.f, 0.f, 0.f);
        #pragma unroll 4
        for (unsigned q = t; q < quads; q += NTHREADS)
            *reinterpret_cast<float4*>(ali + 4u * q) = z4;

        const unsigned tail_start = p + 4u * quads;
        const unsigned ntail = nelem - tail_start;       // 0..3 (incl. last col, half 1)
        if (t < (int)ntail) base[tail_start + t] = 0.f;
    }

    __syncthreads();  // order zero-streams before patches (both segments)

    // Patch seg0 with warps 0-2 (t<72), seg1 with warps 4-6 (t in [128,200)).
    const int pt  = (t < 128) ? t : (t - 128);
    const int pseg = (t < 128) ? 0 : 1;
    if (pt < 72) {
        const unsigned s    = k + (unsigned)pseg * 8192u;
        const unsigned r    = s >> 1;
        const unsigned half = s & 1u;
        float* __restrict__ row = M + (size_t)r * (size_t)COLS;

        const unsigned ci  = r >> 10;
        const unsigned y   = (r >> 5) & 31u;
        const unsigned x   = r & 31u;
        const unsigned c   = 8u * half + (unsigned)pt / 9u;
        const unsigned rem = (unsigned)pt % 9u;
        const unsigned dy  = rem / 3u;
        const unsigned dx  = rem - dy * 3u;
        const int i = (int)y - 1 + (int)dy;
        const int j = (int)x - 1 + (int)dx;
        if ((unsigned)i < 32u && (unsigned)j < 32u) {
            const unsigned kh  = 2u - dy;
            const unsigned kw  = 2u - dx;
            const unsigned col = c * 1024u + (unsigned)i * 32u + (unsigned)j;
            row[col] = __ldg(wgt + ((c * 8u + ci) * 3u + kh) * 3u + kw);
        }
    }
}

extern "C" void kernel_launch(void* const* d_in, const int* in_sizes, int n_in,
                              void* d_out, int out_size) {
    const float* cl   = (const float*)d_in[0];
    const float* cu   = (const float*)d_in[1];
    const float* wgt  = (const float*)d_in[2];
    const float* bias = (const float*)d_in[3];
    float* out = (float*)d_out;

    conv_abs_kernel<<<GRID_TOTAL, NTHREADS>>>(cl, cu, wgt, bias, out);
}